// round 1
// baseline (speedup 1.0000x reference)
#include <cuda_runtime.h>
#include <cuda_bf16.h>

// ---------------------------------------------------------------------------
// NonLocal2D collapsed to per-batch affine map:
//   G[b]   = xf xf^T                (C x C Gram),   s[b] = xf . 1
//   S[b]   = G - s s^T / N
//   M[b]   = phi_w  S  g_w^T        (CI x CI)
//   Q[b]   = out_w  M^T             (C x CI)
//   W[b]   = Q  theta'_w            (C x C)
//   beff[b]= Q theta'_b + out_b
//   out    = x + W xf + beff
// theta'_w = theta_w - colmean(theta_w), theta'_b = theta_b - mean(theta_b)
// g_b and phi_b cancel exactly (spatial centering of phi).
// ---------------------------------------------------------------------------

#define BATCH 4
#define C     256
#define CI    128
#define NSP   4096          // H*W
#define KS    8             // gram split-K factor
#define KCHUNK (NSP / KS)   // 512
#define INV_N (1.0f / 4096.0f)

// scratch (static device allocations; harness forbids cudaMalloc)
__device__ float d_Gp[KS][BATCH][C][C];   // gram partials (8 MB)
__device__ float d_G [BATCH][C][C];
__device__ float d_s [BATCH][C];
__device__ float d_thpw[CI * C];          // theta' weights
__device__ float d_thpb[CI];
__device__ float d_P [BATCH][C][CI];      // S g^T
__device__ float d_M [BATCH][CI][CI];
__device__ float d_Q [BATCH][C][CI];
__device__ float d_W [BATCH][C][C];
__device__ float d_beff[BATCH][C];

// ---------------------------------------------------------------------------
// row sums: s[b][c] = sum_n x[b][c][n]
__global__ void k_rowsum(const float* __restrict__ x) {
    int bc = blockIdx.x;                       // b*C + c
    const float* row = x + (size_t)bc * NSP;
    float acc = 0.f;
    for (int i = threadIdx.x; i < NSP; i += 256) acc += row[i];
    __shared__ float sm[256];
    sm[threadIdx.x] = acc;
    __syncthreads();
    for (int s = 128; s > 0; s >>= 1) {
        if (threadIdx.x < s) sm[threadIdx.x] += sm[threadIdx.x + s];
        __syncthreads();
    }
    if (threadIdx.x == 0) d_s[bc / C][bc % C] = sm[0];
}

// ---------------------------------------------------------------------------
// Gram partials: 128x128 tile, 8x8 per thread, BK=16, split-K over KS chunks.
__global__ void __launch_bounds__(256) k_gram(const float* __restrict__ x) {
    int t  = blockIdx.x;          // 0..3 : 2x2 tiles over 256x256
    int ks = blockIdx.y;
    int b  = blockIdx.z;
    int tr = (t >> 1) * 128, tc = (t & 1) * 128;
    const float* xb = x + (size_t)b * C * NSP;

    __shared__ float As[16][132];
    __shared__ float Bs[16][132];

    int tx = threadIdx.x & 15, ty = threadIdx.x >> 4;
    int kk = (threadIdx.x & 3) * 4;       // 0,4,8,12
    int r0 = threadIdx.x >> 2;            // 0..63
    float acc[8][8] = {};

    int kbase = ks * KCHUNK;
    for (int k0 = 0; k0 < KCHUNK; k0 += 16) {
#pragma unroll
        for (int rr = 0; rr < 2; rr++) {
            int r = r0 + rr * 64;
            float4 va = *(const float4*)(xb + (size_t)(tr + r) * NSP + kbase + k0 + kk);
            As[kk + 0][r] = va.x; As[kk + 1][r] = va.y;
            As[kk + 2][r] = va.z; As[kk + 3][r] = va.w;
            float4 vb = *(const float4*)(xb + (size_t)(tc + r) * NSP + kbase + k0 + kk);
            Bs[kk + 0][r] = vb.x; Bs[kk + 1][r] = vb.y;
            Bs[kk + 2][r] = vb.z; Bs[kk + 3][r] = vb.w;
        }
        __syncthreads();
#pragma unroll
        for (int k = 0; k < 16; k++) {
            float a[8], bb[8];
            *(float4*)(a)     = *(const float4*)&As[k][ty * 8];
            *(float4*)(a + 4) = *(const float4*)&As[k][ty * 8 + 4];
            *(float4*)(bb)     = *(const float4*)&Bs[k][tx * 8];
            *(float4*)(bb + 4) = *(const float4*)&Bs[k][tx * 8 + 4];
#pragma unroll
            for (int i = 0; i < 8; i++)
#pragma unroll
                for (int j = 0; j < 8; j++) acc[i][j] += a[i] * bb[j];
        }
        __syncthreads();
    }
    float* out = &d_Gp[ks][b][0][0];
#pragma unroll
    for (int i = 0; i < 8; i++)
#pragma unroll
        for (int j = 0; j < 8; j++)
            out[(size_t)(tr + ty * 8 + i) * C + tc + tx * 8 + j] = acc[i][j];
}

// deterministic split-K reduce
__global__ void k_gram_reduce() {
    int idx = blockIdx.x * 256 + threadIdx.x;   // over BATCH*C*C = 262144
    const float* gp = &d_Gp[0][0][0][0];
    float a = 0.f;
#pragma unroll
    for (int p = 0; p < KS; p++) a += gp[(size_t)p * (BATCH * C * C) + idx];
    (&d_G[0][0][0])[idx] = a;
}

// ---------------------------------------------------------------------------
// theta' prep (one CTA)
__global__ void k_theta_prep(const float* __restrict__ tw, const float* __restrict__ tb) {
    int c = threadIdx.x;   // 0..255
    float sum = 0.f;
    for (int o = 0; o < CI; o++) sum += tw[o * C + c];
    float mean = sum * (1.0f / CI);
    for (int o = 0; o < CI; o++) d_thpw[o * C + c] = tw[o * C + c] - mean;
    if (c < CI) {
        float sb = 0.f;
        for (int o = 0; o < CI; o++) sb += tb[o];
        d_thpb[c] = tb[c] - sb * (1.0f / CI);
    }
}

// ---------------------------------------------------------------------------
// small chain GEMMs: 32x32 tile, 2x2 per thread, BK=32
// OP 0: P = S g_w^T      (256x128, K=256)  A implicit S, B = g_w (NT)
// OP 1: M = phi_w P      (128x128, K=256)  A = phi_w,   B = P   (NN)
// OP 2: Q = out_w M^T    (256x128, K=128)  A = out_w,   B = M   (NT)
// OP 3: W = Q theta'_w   (256x256, K=128)  A = Q,       B = thpw(NN)
template <int OP>
__device__ __forceinline__ float loadA(const float* __restrict__ w, int b, int m, int k) {
    if (OP == 0) return d_G[b][m][k] - d_s[b][m] * d_s[b][k] * INV_N;
    if (OP == 1) return w[m * C + k];
    if (OP == 2) return w[m * CI + k];
    return d_Q[b][m][k];
}
template <int OP>
__device__ __forceinline__ float loadB(const float* __restrict__ w, int b, int k, int n) {
    if (OP == 0) return w[n * C + k];
    if (OP == 1) return d_P[b][k][n];
    if (OP == 2) return d_M[b][n][k];
    return d_thpw[k * C + n];
}
template <int OP>
__device__ __forceinline__ void storeEl(int b, int m, int n, float v) {
    if (OP == 0) d_P[b][m][n] = v;
    if (OP == 1) d_M[b][m][n] = v;
    if (OP == 2) d_Q[b][m][n] = v;
    if (OP == 3) d_W[b][m][n] = v;
}

template <int OP>
__global__ void __launch_bounds__(256) k_chain(const float* __restrict__ w, int Kd) {
    constexpr bool BT = (OP == 0 || OP == 2);
    int b  = blockIdx.z;
    int m0 = blockIdx.y * 32, n0 = blockIdx.x * 32;
    __shared__ float As[32][33];
    __shared__ float Bs[32][33];
    int tx = threadIdx.x & 15, ty = threadIdx.x >> 4;
    int c0 = threadIdx.x & 31, r0 = threadIdx.x >> 5;
    float a00 = 0.f, a01 = 0.f, a10 = 0.f, a11 = 0.f;

    for (int k0 = 0; k0 < Kd; k0 += 32) {
#pragma unroll
        for (int p = 0; p < 4; p++) {
            int r = r0 + p * 8;
            As[c0][r] = loadA<OP>(w, b, m0 + r, k0 + c0);
            if (BT) Bs[c0][r] = loadB<OP>(w, b, k0 + c0, n0 + r);
            else    Bs[r][c0] = loadB<OP>(w, b, k0 + r, n0 + c0);
        }
        __syncthreads();
#pragma unroll
        for (int k = 0; k < 32; k++) {
            float a0 = As[k][ty * 2], a1 = As[k][ty * 2 + 1];
            float b0 = Bs[k][tx * 2], b1 = Bs[k][tx * 2 + 1];
            a00 += a0 * b0; a01 += a0 * b1; a10 += a1 * b0; a11 += a1 * b1;
        }
        __syncthreads();
    }
    storeEl<OP>(b, m0 + ty * 2,     n0 + tx * 2,     a00);
    storeEl<OP>(b, m0 + ty * 2,     n0 + tx * 2 + 1, a01);
    storeEl<OP>(b, m0 + ty * 2 + 1, n0 + tx * 2,     a10);
    storeEl<OP>(b, m0 + ty * 2 + 1, n0 + tx * 2 + 1, a11);
}

// ---------------------------------------------------------------------------
__global__ void k_beff(const float* __restrict__ out_b) {
    int b = blockIdx.x, o = threadIdx.x;   // 256 threads
    float acc = out_b[o];
    for (int oo = 0; oo < CI; oo++) acc += d_Q[b][o][oo] * d_thpb[oo];
    d_beff[b][o] = acc;
}

// ---------------------------------------------------------------------------
// apply: out[b][o][n] = x[b][o][n] + beff[b][o] + sum_c W[b][o][c] x[b][c][n]
// 128x128 tile, 8x8 per thread, BK=16, K=256.
__global__ void __launch_bounds__(256) k_apply(const float* __restrict__ x,
                                               float* __restrict__ outp) {
    int b  = blockIdx.z;
    int m0 = blockIdx.y * 128;   // channel tile
    int n0 = blockIdx.x * 128;   // spatial tile
    const float* xb = x + (size_t)b * C * NSP;
    float* ob = outp + (size_t)b * C * NSP;
    const float* Wb = &d_W[b][0][0];

    __shared__ float As[16][132];   // As[k][i] = W[m0+i][k0+k]
    __shared__ float Bs[16][128];   // Bs[k][j] = x[k0+k][n0+j]

    int tx  = threadIdx.x & 15, ty = threadIdx.x >> 4;
    int kkA = (threadIdx.x & 3) * 4, rA = threadIdx.x >> 2;
    int jB  = (threadIdx.x & 31) * 4, kB = threadIdx.x >> 5;
    float acc[8][8] = {};

    for (int k0 = 0; k0 < C; k0 += 16) {
#pragma unroll
        for (int rr = 0; rr < 2; rr++) {
            int r = rA + rr * 64;
            float4 va = *(const float4*)(Wb + (size_t)(m0 + r) * C + k0 + kkA);
            As[kkA + 0][r] = va.x; As[kkA + 1][r] = va.y;
            As[kkA + 2][r] = va.z; As[kkA + 3][r] = va.w;
            int k = kB + rr * 8;
            float4 vb = *(const float4*)(xb + (size_t)(k0 + k) * NSP + n0 + jB);
            *(float4*)&Bs[k][jB] = vb;
        }
        __syncthreads();
#pragma unroll
        for (int k = 0; k < 16; k++) {
            float a[8], bb[8];
            *(float4*)(a)     = *(const float4*)&As[k][ty * 8];
            *(float4*)(a + 4) = *(const float4*)&As[k][ty * 8 + 4];
            *(float4*)(bb)     = *(const float4*)&Bs[k][tx * 8];
            *(float4*)(bb + 4) = *(const float4*)&Bs[k][tx * 8 + 4];
#pragma unroll
            for (int i = 0; i < 8; i++)
#pragma unroll
                for (int j = 0; j < 8; j++) acc[i][j] += a[i] * bb[j];
        }
        __syncthreads();
    }

#pragma unroll
    for (int i = 0; i < 8; i++) {
        int row = m0 + ty * 8 + i;
        float be = d_beff[b][row];
        size_t base = (size_t)row * NSP + n0 + tx * 8;
#pragma unroll
        for (int j = 0; j < 8; j += 4) {
            float4 xv = *(const float4*)(xb + base + j);
            float4 o;
            o.x = acc[i][j + 0] + xv.x + be;
            o.y = acc[i][j + 1] + xv.y + be;
            o.z = acc[i][j + 2] + xv.z + be;
            o.w = acc[i][j + 3] + xv.w + be;
            *(float4*)(ob + base + j) = o;
        }
    }
}

// ---------------------------------------------------------------------------
extern "C" void kernel_launch(void* const* d_in, const int* in_sizes, int n_in,
                              void* d_out, int out_size) {
    const float* x       = (const float*)d_in[0];
    const float* g_w     = (const float*)d_in[1];
    // d_in[2] = g_b   : cancels exactly
    const float* theta_w = (const float*)d_in[3];
    const float* theta_b = (const float*)d_in[4];
    const float* phi_w   = (const float*)d_in[5];
    // d_in[6] = phi_b : cancels exactly
    const float* out_w   = (const float*)d_in[7];
    const float* out_b   = (const float*)d_in[8];
    float* out = (float*)d_out;

    k_rowsum<<<BATCH * C, 256>>>(x);
    k_gram<<<dim3(4, KS, BATCH), 256>>>(x);
    k_gram_reduce<<<1024, 256>>>();
    k_theta_prep<<<1, 256>>>(theta_w, theta_b);

    k_chain<0><<<dim3(CI / 32, C  / 32, BATCH), 256>>>(g_w,   C);   // P = S g^T
    k_chain<1><<<dim3(CI / 32, CI / 32, BATCH), 256>>>(phi_w, C);   // M = phi P
    k_chain<2><<<dim3(CI / 32, C  / 32, BATCH), 256>>>(out_w, CI);  // Q = out_w M^T
    k_beff<<<BATCH, 256>>>(out_b);
    k_chain<3><<<dim3(C / 32,  C  / 32, BATCH), 256>>>(nullptr, CI); // W = Q theta'

    k_apply<<<dim3(NSP / 128, C / 128, BATCH), 256>>>(x, out);
}

// round 5
// speedup vs baseline: 1.5460x; 1.5460x over previous
#include <cuda_runtime.h>
#include <cuda_bf16.h>
#include <cstdint>

// ---------------------------------------------------------------------------
// NonLocal2D collapsed to per-batch affine map (see R1):
//   G = x x^T, S = G - s s^T/N, M = phi S g^T, Q = out_w M^T, W = Q theta',
//   out = x + W x + beff.
// Large GEMMs (Gram, apply) on tensor cores via legacy mma.sync bf16
// (m16n8k16, fp32 accum) with hi/lo split: 3 passes hi*hi + hi*lo + lo*hi.
// tcgen05 is NOT available (harness PTX target is compute_103, no 'a').
// ---------------------------------------------------------------------------

#define BATCH 4
#define C     256
#define CI    128
#define NSP   4096
#define KS    16
#define KCHUNK (NSP / KS)      // 256
#define INV_N (1.0f / 4096.0f)
#define GR_PAD 40              // A-tile row stride (bf16): 80B, ldmatrix conflict-free
#define AP_BPAD 136            // x-tile row stride (bf16): 272B, conflict-free

// ------------------------- device scratch ----------------------------------
__device__ __nv_bfloat16 d_xhi [BATCH][C][NSP];
__device__ __nv_bfloat16 d_xlo [BATCH][C][NSP];
__device__ float d_Gp[KS][BATCH][3][128][128];
__device__ float d_G [BATCH][C][C];
__device__ float d_s [BATCH][C];
__device__ float d_thpw[CI * C];
__device__ float d_thpb[CI];
__device__ float d_P [BATCH][C][CI];
__device__ float d_M [BATCH][CI][CI];
__device__ float d_Q [BATCH][C][CI];
__device__ float d_W [BATCH][C][C];
__device__ __nv_bfloat16 d_Whi[BATCH][C][C];
__device__ __nv_bfloat16 d_Wlo[BATCH][C][C];
__device__ float d_beff[BATCH][C];

// ------------------------- mma/ldmatrix helpers ----------------------------
__device__ __forceinline__ uint32_t smem_u32(const void* p) {
    uint32_t a;
    asm("{ .reg .u64 t; cvta.to.shared.u64 t, %1; cvt.u32.u64 %0, t; }"
        : "=r"(a) : "l"(p));
    return a;
}
__device__ __forceinline__ void ldsm_x4(uint32_t* r, uint32_t addr) {
    asm volatile("ldmatrix.sync.aligned.m8n8.x4.shared.b16 {%0,%1,%2,%3}, [%4];"
                 : "=r"(r[0]), "=r"(r[1]), "=r"(r[2]), "=r"(r[3]) : "r"(addr));
}
__device__ __forceinline__ void ldsm_x4_t(uint32_t* r, uint32_t addr) {
    asm volatile("ldmatrix.sync.aligned.m8n8.x4.trans.shared.b16 {%0,%1,%2,%3}, [%4];"
                 : "=r"(r[0]), "=r"(r[1]), "=r"(r[2]), "=r"(r[3]) : "r"(addr));
}
__device__ __forceinline__ void mma16816(float* d, const uint32_t* a, const uint32_t* b) {
    asm volatile(
        "mma.sync.aligned.m16n8k16.row.col.f32.bf16.bf16.f32 "
        "{%0,%1,%2,%3}, {%4,%5,%6,%7}, {%8,%9}, {%0,%1,%2,%3};"
        : "+f"(d[0]), "+f"(d[1]), "+f"(d[2]), "+f"(d[3])
        : "r"(a[0]), "r"(a[1]), "r"(a[2]), "r"(a[3]), "r"(b[0]), "r"(b[1]));
}

// ---------------------------------------------------------------------------
// convert: x fp32 -> bf16 hi/lo, [c][n] layout only (mma.row.col needs no xT)
__global__ void __launch_bounds__(256) k_convert(const float* __restrict__ x) {
    size_t i4 = ((size_t)blockIdx.x * 256 + threadIdx.x) * 4;  // over 4M elems
    float4 v = *(const float4*)(x + i4);
    float f[4] = {v.x, v.y, v.z, v.w};
    __nv_bfloat16 h[4], l[4];
#pragma unroll
    for (int j = 0; j < 4; j++) {
        h[j] = __float2bfloat16(f[j]);
        l[j] = __float2bfloat16(f[j] - __bfloat162float(h[j]));
    }
    *(uint2*)((&d_xhi[0][0][0]) + i4) = *(uint2*)h;
    *(uint2*)((&d_xlo[0][0][0]) + i4) = *(uint2*)l;
}

// ---------------------------------------------------------------------------
__global__ void k_rowsum(const float* __restrict__ x) {
    int bc = blockIdx.x;
    const float* row = x + (size_t)bc * NSP;
    float acc = 0.f;
    for (int i = threadIdx.x; i < NSP; i += 256) acc += row[i];
    __shared__ float sm[256];
    sm[threadIdx.x] = acc;
    __syncthreads();
    for (int s = 128; s > 0; s >>= 1) {
        if (threadIdx.x < s) sm[threadIdx.x] += sm[threadIdx.x + s];
        __syncthreads();
    }
    if (threadIdx.x == 0) d_s[bc / C][bc % C] = sm[0];
}

// ---------------------------------------------------------------------------
// Gram via mma.sync: CTA = one 128x128 tile of G (3 unique symmetric tiles),
// split-K over KS chunks. 8 warps, warp tile 64x32, BK=32.
__global__ void __launch_bounds__(256) k_gram_mma() {
    __shared__ __nv_bfloat16 sA[2][128][GR_PAD];
    __shared__ __nv_bfloat16 sB[2][128][GR_PAD];
    const int tid = threadIdx.x, wid = tid >> 5, lane = tid & 31;
    const int t = blockIdx.x, ks = blockIdx.y, b = blockIdx.z;
    const int tr = (t == 2) ? 128 : 0, tc = (t == 0) ? 0 : 128;
    const bool diag = (t != 1);
    const int wm = (wid & 1) * 64, wn = (wid >> 1) * 32;
    float acc[4][4][4] = {};

    const uint32_t sAu = smem_u32(&sA[0][0][0]);
    const uint32_t sBu = diag ? sAu : smem_u32(&sB[0][0][0]);
    const uint32_t loA = 128 * GR_PAD * 2;   // hi->lo plane byte offset
    const int kbase = ks * KCHUNK;

    for (int kc = 0; kc < KCHUNK; kc += 32) {
#pragma unroll
        for (int it = 0; it < 2; it++) {
            int i = tid + it * 256;            // 0..511
            int r = i >> 2, sg = (i & 3) * 8;
            *(uint4*)&sA[0][r][sg] = *(const uint4*)&d_xhi[b][tr + r][kbase + kc + sg];
            *(uint4*)&sA[1][r][sg] = *(const uint4*)&d_xlo[b][tr + r][kbase + kc + sg];
            if (!diag) {
                *(uint4*)&sB[0][r][sg] = *(const uint4*)&d_xhi[b][tc + r][kbase + kc + sg];
                *(uint4*)&sB[1][r][sg] = *(const uint4*)&d_xlo[b][tc + r][kbase + kc + sg];
            }
        }
        __syncthreads();
#pragma unroll
        for (int kk = 0; kk < 32; kk += 16) {
            uint32_t ah[4][4], al[4][4], bh[2][4], bl[2][4];
            const int arow = lane & 15, acol = kk + (lane >> 4) * 8;
#pragma unroll
            for (int i = 0; i < 4; i++) {
                uint32_t ad = sAu + (uint32_t)((wm + i * 16 + arow) * GR_PAD + acol) * 2;
                ldsm_x4(ah[i], ad);
                ldsm_x4(al[i], ad + loA);
            }
            const int bn = (lane & 7) + (lane >> 4) * 8;
            const int bcol = kk + ((lane >> 3) & 1) * 8;
#pragma unroll
            for (int j = 0; j < 2; j++) {
                uint32_t bd = sBu + (uint32_t)((wn + j * 16 + bn) * GR_PAD + bcol) * 2;
                ldsm_x4(bh[j], bd);
                ldsm_x4(bl[j], bd + loA);
            }
#pragma unroll
            for (int i = 0; i < 4; i++)
#pragma unroll
                for (int jj = 0; jj < 4; jj++) {
                    const uint32_t* ph = &bh[jj >> 1][(jj & 1) * 2];
                    const uint32_t* pl = &bl[jj >> 1][(jj & 1) * 2];
                    mma16816(acc[i][jj], ah[i], ph);
                    mma16816(acc[i][jj], ah[i], pl);
                    mma16816(acc[i][jj], al[i], ph);
                }
        }
        __syncthreads();
    }
#pragma unroll
    for (int i = 0; i < 4; i++)
#pragma unroll
        for (int jj = 0; jj < 4; jj++) {
            int rl = wm + i * 16 + (lane >> 2);
            int cl = wn + jj * 8 + (lane & 3) * 2;
            *(float2*)&d_Gp[ks][b][t][rl][cl]     = make_float2(acc[i][jj][0], acc[i][jj][1]);
            *(float2*)&d_Gp[ks][b][t][rl + 8][cl] = make_float2(acc[i][jj][2], acc[i][jj][3]);
        }
}

__global__ void k_gram_reduce() {
    int idx = blockIdx.x * 256 + threadIdx.x;      // BATCH*3*128*128
    int col = idx & 127, row = (idx >> 7) & 127;
    int t = (idx >> 14) % 3, b = idx / (3 * 16384);
    float a = 0.f;
#pragma unroll
    for (int p = 0; p < KS; p++) a += d_Gp[p][b][t][row][col];
    int R = ((t == 2) ? 128 : 0) + row;
    int Cc = ((t == 0) ? 0 : 128) + col;
    d_G[b][R][Cc] = a;
    if (t == 1) d_G[b][Cc][R] = a;
}

// ---------------------------------------------------------------------------
__global__ void k_theta_prep(const float* __restrict__ tw, const float* __restrict__ tb) {
    const int c = blockIdx.x, o = threadIdx.x;     // 256 blocks x 128 threads
    __shared__ float sm[128];
    float v = tw[o * C + c];
    sm[o] = v; __syncthreads();
    for (int s = 64; s > 0; s >>= 1) { if (o < s) sm[o] += sm[o + s]; __syncthreads(); }
    d_thpw[o * C + c] = v - sm[0] * (1.0f / CI);
    if (c == 0) {
        float vb = tb[o];
        __syncthreads();
        sm[o] = vb; __syncthreads();
        for (int s = 64; s > 0; s >>= 1) { if (o < s) sm[o] += sm[o + s]; __syncthreads(); }
        d_thpb[o] = vb - sm[0] * (1.0f / CI);
    }
}

// ---------------------------------------------------------------------------
// small fp32 chain GEMMs (tiny; unchanged from R1)
template <int OP>
__device__ __forceinline__ float loadA(const float* __restrict__ w, int b, int m, int k) {
    if (OP == 0) return d_G[b][m][k] - d_s[b][m] * d_s[b][k] * INV_N;
    if (OP == 1) return w[m * C + k];
    if (OP == 2) return w[m * CI + k];
    return d_Q[b][m][k];
}
template <int OP>
__device__ __forceinline__ float loadB(const float* __restrict__ w, int b, int k, int n) {
    if (OP == 0) return w[n * C + k];
    if (OP == 1) return d_P[b][k][n];
    if (OP == 2) return d_M[b][n][k];
    return d_thpw[k * C + n];
}
template <int OP>
__device__ __forceinline__ void storeEl(int b, int m, int n, float v) {
    if (OP == 0) d_P[b][m][n] = v;
    if (OP == 1) d_M[b][m][n] = v;
    if (OP == 2) d_Q[b][m][n] = v;
    if (OP == 3) d_W[b][m][n] = v;
}
template <int OP>
__global__ void __launch_bounds__(256) k_chain(const float* __restrict__ w, int Kd) {
    constexpr bool BT = (OP == 0 || OP == 2);
    int b = blockIdx.z;
    int m0 = blockIdx.y * 32, n0 = blockIdx.x * 32;
    __shared__ float As[32][33];
    __shared__ float Bs[32][33];
    int tx = threadIdx.x & 15, ty = threadIdx.x >> 4;
    int c0 = threadIdx.x & 31, r0 = threadIdx.x >> 5;
    float a00 = 0.f, a01 = 0.f, a10 = 0.f, a11 = 0.f;
    for (int k0 = 0; k0 < Kd; k0 += 32) {
#pragma unroll
        for (int p = 0; p < 4; p++) {
            int r = r0 + p * 8;
            As[c0][r] = loadA<OP>(w, b, m0 + r, k0 + c0);
            if (BT) Bs[c0][r] = loadB<OP>(w, b, k0 + c0, n0 + r);
            else    Bs[r][c0] = loadB<OP>(w, b, k0 + r, n0 + c0);
        }
        __syncthreads();
#pragma unroll
        for (int k = 0; k < 32; k++) {
            float a0 = As[k][ty * 2], a1 = As[k][ty * 2 + 1];
            float b0 = Bs[k][tx * 2], b1 = Bs[k][tx * 2 + 1];
            a00 += a0 * b0; a01 += a0 * b1; a10 += a1 * b0; a11 += a1 * b1;
        }
        __syncthreads();
    }
    storeEl<OP>(b, m0 + ty * 2,     n0 + tx * 2,     a00);
    storeEl<OP>(b, m0 + ty * 2,     n0 + tx * 2 + 1, a01);
    storeEl<OP>(b, m0 + ty * 2 + 1, n0 + tx * 2,     a10);
    storeEl<OP>(b, m0 + ty * 2 + 1, n0 + tx * 2 + 1, a11);
}

__global__ void k_beff(const float* __restrict__ out_b) {
    int b = blockIdx.x, o = threadIdx.x;
    float acc = out_b[o];
    for (int oo = 0; oo < CI; oo++) acc += d_Q[b][o][oo] * d_thpb[oo];
    d_beff[b][o] = acc;
}

__global__ void k_wsplit() {
    int idx = blockIdx.x * 256 + threadIdx.x;      // BATCH*C*C
    float w = (&d_W[0][0][0])[idx];
    __nv_bfloat16 h = __float2bfloat16(w);
    (&d_Whi[0][0][0])[idx] = h;
    (&d_Wlo[0][0][0])[idx] = __float2bfloat16(w - __bfloat162float(h));
}

// ---------------------------------------------------------------------------
// apply via mma.sync: out = x + W x + beff. CTA tile 128(ch) x 128(sp), K=256.
// 8 warps, warp tile 64x32. B (=x) fragments via ldmatrix.trans.
__global__ void __launch_bounds__(256) k_apply_mma(const float* __restrict__ x,
                                                   float* __restrict__ outp) {
    __shared__ __nv_bfloat16 sW[2][128][GR_PAD];
    __shared__ __nv_bfloat16 sX[2][32][AP_BPAD];
    const int tid = threadIdx.x, wid = tid >> 5, lane = tid & 31;
    const int m0 = blockIdx.y * 128, n0 = blockIdx.x * 128, b = blockIdx.z;
    const int wm = (wid & 1) * 64, wn = (wid >> 1) * 32;
    float acc[4][4][4] = {};

    const uint32_t sWu = smem_u32(&sW[0][0][0]);
    const uint32_t sXu = smem_u32(&sX[0][0][0]);
    const uint32_t loW = 128 * GR_PAD * 2;
    const uint32_t loX = 32 * AP_BPAD * 2;

    for (int kc = 0; kc < C; kc += 32) {
#pragma unroll
        for (int it = 0; it < 2; it++) {
            int i = tid + it * 256;
            int r = i >> 2, sg = (i & 3) * 8;            // W tile 128x32
            *(uint4*)&sW[0][r][sg] = *(const uint4*)&d_Whi[b][m0 + r][kc + sg];
            *(uint4*)&sW[1][r][sg] = *(const uint4*)&d_Wlo[b][m0 + r][kc + sg];
            int xr = i >> 4, xs = (i & 15) * 8;          // x tile 32x128
            *(uint4*)&sX[0][xr][xs] = *(const uint4*)&d_xhi[b][kc + xr][n0 + xs];
            *(uint4*)&sX[1][xr][xs] = *(const uint4*)&d_xlo[b][kc + xr][n0 + xs];
        }
        __syncthreads();
#pragma unroll
        for (int kk = 0; kk < 32; kk += 16) {
            uint32_t ah[4][4], al[4][4], bh[2][4], bl[2][4];
            const int arow = lane & 15, acol = kk + (lane >> 4) * 8;
#pragma unroll
            for (int i = 0; i < 4; i++) {
                uint32_t ad = sWu + (uint32_t)((wm + i * 16 + arow) * GR_PAD + acol) * 2;
                ldsm_x4(ah[i], ad);
                ldsm_x4(al[i], ad + loW);
            }
            const int krow = kk + (lane & 7) + ((lane >> 3) & 1) * 8;
            const int ncol = ((lane >> 4) & 1) * 8;
#pragma unroll
            for (int j = 0; j < 2; j++) {
                uint32_t bd = sXu + (uint32_t)(krow * AP_BPAD + wn + j * 16 + ncol) * 2;
                ldsm_x4_t(bh[j], bd);
                ldsm_x4_t(bl[j], bd + loX);
            }
#pragma unroll
            for (int i = 0; i < 4; i++)
#pragma unroll
                for (int jj = 0; jj < 4; jj++) {
                    const uint32_t* ph = &bh[jj >> 1][(jj & 1) * 2];
                    const uint32_t* pl = &bl[jj >> 1][(jj & 1) * 2];
                    mma16816(acc[i][jj], ah[i], ph);
                    mma16816(acc[i][jj], ah[i], pl);
                    mma16816(acc[i][jj], al[i], ph);
                }
        }
        __syncthreads();
    }
    // epilogue: + x + beff
#pragma unroll
    for (int i = 0; i < 4; i++) {
        int r0g = m0 + wm + i * 16 + (lane >> 2);
        float be0 = d_beff[b][r0g], be1 = d_beff[b][r0g + 8];
        const float* x0 = x + ((size_t)b * C + r0g) * NSP + n0;
        float* o0 = outp + ((size_t)b * C + r0g) * NSP + n0;
#pragma unroll
        for (int jj = 0; jj < 4; jj++) {
            int cl = wn + jj * 8 + (lane & 3) * 2;
            float2 xa = *(const float2*)(x0 + cl);
            float2 xb = *(const float2*)(x0 + 8 * NSP + cl);
            float2 oa = make_float2(acc[i][jj][0] + xa.x + be0, acc[i][jj][1] + xa.y + be0);
            float2 ob = make_float2(acc[i][jj][2] + xb.x + be1, acc[i][jj][3] + xb.y + be1);
            *(float2*)(o0 + cl) = oa;
            *(float2*)(o0 + 8 * NSP + cl) = ob;
        }
    }
}

// ---------------------------------------------------------------------------
extern "C" void kernel_launch(void* const* d_in, const int* in_sizes, int n_in,
                              void* d_out, int out_size) {
    const float* x       = (const float*)d_in[0];
    const float* g_w     = (const float*)d_in[1];
    const float* theta_w = (const float*)d_in[3];
    const float* theta_b = (const float*)d_in[4];
    const float* phi_w   = (const float*)d_in[5];
    const float* out_w   = (const float*)d_in[7];
    const float* out_b   = (const float*)d_in[8];
    float* out = (float*)d_out;

    k_convert<<<(BATCH * C * NSP) / 1024, 256>>>(x);
    k_rowsum<<<BATCH * C, 256>>>(x);
    k_gram_mma<<<dim3(3, KS, BATCH), 256>>>();
    k_gram_reduce<<<(BATCH * 3 * 128 * 128) / 256, 256>>>();
    k_theta_prep<<<C, 128>>>(theta_w, theta_b);

    k_chain<0><<<dim3(CI / 32, C  / 32, BATCH), 256>>>(g_w,   C);   // P = S g^T
    k_chain<1><<<dim3(CI / 32, CI / 32, BATCH), 256>>>(phi_w, C);   // M = phi P
    k_chain<2><<<dim3(CI / 32, C  / 32, BATCH), 256>>>(out_w, CI);  // Q = out_w M^T
    k_beff<<<BATCH, 256>>>(out_b);
    k_chain<3><<<dim3(C / 32,  C  / 32, BATCH), 256>>>(nullptr, CI); // W = Q theta'
    k_wsplit<<<(BATCH * C * C) / 256, 256>>>();

    k_apply_mma<<<dim3(NSP / 128, C / 128, BATCH), 256>>>(x, out);
}

// round 7
// speedup vs baseline: 1.7058x; 1.1033x over previous
#include <cuda_runtime.h>
#include <cuda_bf16.h>
#include <cstdint>

// ---------------------------------------------------------------------------
// NonLocal2D collapsed to per-batch affine map:
//   G = x x^T, S = G - s s^T/N, M = phi S g^T, Q = out_w M^T, W = Q theta',
//   out = x + W x + beff.
// Large GEMMs (Gram, apply) on tensor cores via legacy mma.sync bf16
// (m16n8k16, fp32 accum) with hi/lo split: hi*hi + hi*lo + lo*hi.
// R5: single-wave gram (KS=12), cp.async double-buffered mainloops,
//     convert+rowsum fused, wsplit folded into chain<3>.
// ---------------------------------------------------------------------------

#define BATCH 4
#define C     256
#define CI    128
#define NSP   4096
#define KS    12
#define INV_N (1.0f / 4096.0f)
#define GR_PAD 40              // bf16 row stride 80B: ldmatrix conflict-free
#define AP_BPAD 136            // bf16 row stride 272B: trans-ldmatrix conflict-free

// ------------------------- device scratch ----------------------------------
__device__ __nv_bfloat16 d_xhi [BATCH][C][NSP];
__device__ __nv_bfloat16 d_xlo [BATCH][C][NSP];
__device__ float d_Gp[KS][BATCH][3][128][128];
__device__ float d_G [BATCH][C][C];
__device__ float d_s [BATCH][C];
__device__ float d_thpw[CI * C];
__device__ float d_thpb[CI];
__device__ float d_P [BATCH][C][CI];
__device__ float d_M [BATCH][CI][CI];
__device__ float d_Q [BATCH][C][CI];
__device__ __nv_bfloat16 d_Whi[BATCH][C][C];
__device__ __nv_bfloat16 d_Wlo[BATCH][C][C];
__device__ float d_beff[BATCH][C];

// ------------------------- helpers -----------------------------------------
__device__ __forceinline__ uint32_t smem_u32(const void* p) {
    uint32_t a;
    asm("{ .reg .u64 t; cvta.to.shared.u64 t, %1; cvt.u32.u64 %0, t; }"
        : "=r"(a) : "l"(p));
    return a;
}
__device__ __forceinline__ void ldsm_x4(uint32_t* r, uint32_t addr) {
    asm volatile("ldmatrix.sync.aligned.m8n8.x4.shared.b16 {%0,%1,%2,%3}, [%4];"
                 : "=r"(r[0]), "=r"(r[1]), "=r"(r[2]), "=r"(r[3]) : "r"(addr));
}
__device__ __forceinline__ void ldsm_x4_t(uint32_t* r, uint32_t addr) {
    asm volatile("ldmatrix.sync.aligned.m8n8.x4.trans.shared.b16 {%0,%1,%2,%3}, [%4];"
                 : "=r"(r[0]), "=r"(r[1]), "=r"(r[2]), "=r"(r[3]) : "r"(addr));
}
__device__ __forceinline__ void mma16816(float* d, const uint32_t* a, const uint32_t* b) {
    asm volatile(
        "mma.sync.aligned.m16n8k16.row.col.f32.bf16.bf16.f32 "
        "{%0,%1,%2,%3}, {%4,%5,%6,%7}, {%8,%9}, {%0,%1,%2,%3};"
        : "+f"(d[0]), "+f"(d[1]), "+f"(d[2]), "+f"(d[3])
        : "r"(a[0]), "r"(a[1]), "r"(a[2]), "r"(a[3]), "r"(b[0]), "r"(b[1]));
}
__device__ __forceinline__ void cp16(uint32_t s, const void* g) {
    asm volatile("cp.async.cg.shared.global [%0], [%1], 16;"
                 :: "r"(s), "l"(__cvta_generic_to_global(g)) : "memory");
}
__device__ __forceinline__ void cp_commit() {
    asm volatile("cp.async.commit_group;" ::: "memory");
}
template <int N> __device__ __forceinline__ void cp_wait() {
    asm volatile("cp.async.wait_group %0;" :: "n"(N) : "memory");
}

// ---------------------------------------------------------------------------
// fused convert + rowsum: x fp32 -> bf16 hi/lo [c][n]; s[b][c] = row sums.
__global__ void __launch_bounds__(256) k_convert_rowsum(const float* __restrict__ x) {
    const int bc0 = blockIdx.x * 2;
    const int tid = threadIdx.x;
    float psum[2] = {0.f, 0.f};
#pragma unroll
    for (int rr = 0; rr < 2; rr++) {
        const float4* row = (const float4*)(x + (size_t)(bc0 + rr) * NSP);
        __nv_bfloat16* hp = (&d_xhi[0][0][0]) + (size_t)(bc0 + rr) * NSP;
        __nv_bfloat16* lp = (&d_xlo[0][0][0]) + (size_t)(bc0 + rr) * NSP;
        for (int i = tid; i < NSP / 4; i += 256) {
            float4 v = row[i];
            float f[4] = {v.x, v.y, v.z, v.w};
            __nv_bfloat16 h[4], l[4];
#pragma unroll
            for (int j = 0; j < 4; j++) {
                h[j] = __float2bfloat16(f[j]);
                l[j] = __float2bfloat16(f[j] - __bfloat162float(h[j]));
            }
            *(uint2*)(hp + i * 4) = *(uint2*)h;
            *(uint2*)(lp + i * 4) = *(uint2*)l;
            psum[rr] += f[0] + f[1] + f[2] + f[3];
        }
    }
    __shared__ float sm[2][256];
    sm[0][tid] = psum[0]; sm[1][tid] = psum[1];
    __syncthreads();
    for (int s = 128; s > 0; s >>= 1) {
        if (tid < s) { sm[0][tid] += sm[0][tid + s]; sm[1][tid] += sm[1][tid + s]; }
        __syncthreads();
    }
    if (tid == 0) {
        (&d_s[0][0])[bc0]     = sm[0][0];
        (&d_s[0][0])[bc0 + 1] = sm[1][0];
    }
}

// ---------------------------------------------------------------------------
// Gram: CTA = one 128x128 tile of G (3 unique symmetric tiles), split-K over
// KS=12 (single wave: 144 CTAs). cp.async double buffered, BK=32.
#define GRAM_STAGE 40960u
#define GRAM_DYN   (2 * 40960)
__global__ void __launch_bounds__(256) k_gram_mma() {
    extern __shared__ char smem_[];
    const int tid = threadIdx.x, wid = tid >> 5, lane = tid & 31;
    const int t = blockIdx.x, ks = blockIdx.y, b = blockIdx.z;
    const int tr = (t == 2) ? 128 : 0, tc = (t == 0) ? 0 : 128;
    const bool diag = (t != 1);
    const int wm = (wid & 1) * 64, wn = (wid >> 1) * 32;
    float acc[4][4][4] = {};
    const uint32_t sb = smem_u32(smem_);
    // 128 k-tiles (32 wide) distributed: first 8 ks get 11, last 4 get 10
    const int base = ks * 10 + (ks < 8 ? ks : 8);
    const int cnt  = (ks < 8) ? 11 : 10;

    auto issue = [&](int c, int st) {
        const int kb = (base + c) * 32;
        const uint32_t ss = sb + (uint32_t)st * GRAM_STAGE;
#pragma unroll
        for (int it = 0; it < 2; it++) {
            int i = tid + it * 256;
            int r = i >> 2, sg = (i & 3) * 8;
            uint32_t so = ss + (uint32_t)(r * GR_PAD + sg) * 2;
            cp16(so,           &d_xhi[b][tr + r][kb + sg]);
            cp16(so + 10240u,  &d_xlo[b][tr + r][kb + sg]);
            if (!diag) {
                cp16(so + 20480u, &d_xhi[b][tc + r][kb + sg]);
                cp16(so + 30720u, &d_xlo[b][tc + r][kb + sg]);
            }
        }
        cp_commit();
    };

    issue(0, 0);
    for (int c = 0; c < cnt; c++) {
        const int st = c & 1;
        if (c + 1 < cnt) { issue(c + 1, st ^ 1); cp_wait<1>(); }
        else             { cp_wait<0>(); }
        __syncthreads();
        const uint32_t sAu = sb + (uint32_t)st * GRAM_STAGE;
        const uint32_t sBu = diag ? sAu : (sAu + 20480u);
#pragma unroll
        for (int kk = 0; kk < 32; kk += 16) {
            uint32_t ah[4][4], al[4][4], bh[2][4], bl[2][4];
            const int arow = lane & 15, acol = kk + (lane >> 4) * 8;
#pragma unroll
            for (int i = 0; i < 4; i++) {
                uint32_t ad = sAu + (uint32_t)((wm + i * 16 + arow) * GR_PAD + acol) * 2;
                ldsm_x4(ah[i], ad);
                ldsm_x4(al[i], ad + 10240u);
            }
            const int bn = (lane & 7) + (lane >> 4) * 8;
            const int bcol = kk + ((lane >> 3) & 1) * 8;
#pragma unroll
            for (int j = 0; j < 2; j++) {
                uint32_t bd = sBu + (uint32_t)((wn + j * 16 + bn) * GR_PAD + bcol) * 2;
                ldsm_x4(bh[j], bd);
                ldsm_x4(bl[j], bd + 10240u);
            }
#pragma unroll
            for (int i = 0; i < 4; i++)
#pragma unroll
                for (int jj = 0; jj < 4; jj++) {
                    const uint32_t* ph = &bh[jj >> 1][(jj & 1) * 2];
                    const uint32_t* pl = &bl[jj >> 1][(jj & 1) * 2];
                    mma16816(acc[i][jj], ah[i], ph);
                    mma16816(acc[i][jj], ah[i], pl);
                    mma16816(acc[i][jj], al[i], ph);
                }
        }
        __syncthreads();
    }
#pragma unroll
    for (int i = 0; i < 4; i++)
#pragma unroll
        for (int jj = 0; jj < 4; jj++) {
            int rl = wm + i * 16 + (lane >> 2);
            int cl = wn + jj * 8 + (lane & 3) * 2;
            *(float2*)&d_Gp[ks][b][t][rl][cl]     = make_float2(acc[i][jj][0], acc[i][jj][1]);
            *(float2*)&d_Gp[ks][b][t][rl + 8][cl] = make_float2(acc[i][jj][2], acc[i][jj][3]);
        }
}

__global__ void k_gram_reduce() {
    int idx = blockIdx.x * 256 + threadIdx.x;      // BATCH*3*128*128
    int col = idx & 127, row = (idx >> 7) & 127;
    int t = (idx >> 14) % 3, b = idx / (3 * 16384);
    float a = 0.f;
#pragma unroll
    for (int p = 0; p < KS; p++) a += d_Gp[p][b][t][row][col];
    int R = ((t == 2) ? 128 : 0) + row;
    int Cc = ((t == 0) ? 0 : 128) + col;
    d_G[b][R][Cc] = a;
    if (t == 1) d_G[b][Cc][R] = a;
}

// ---------------------------------------------------------------------------
__global__ void k_theta_prep(const float* __restrict__ tw, const float* __restrict__ tb) {
    const int c = blockIdx.x, o = threadIdx.x;     // 256 blocks x 128 threads
    __shared__ float sm[128];
    float v = tw[o * C + c];
    sm[o] = v; __syncthreads();
    for (int s = 64; s > 0; s >>= 1) { if (o < s) sm[o] += sm[o + s]; __syncthreads(); }
    d_thpw[o * C + c] = v - sm[0] * (1.0f / CI);
    if (c == 0) {
        float vb = tb[o];
        __syncthreads();
        sm[o] = vb; __syncthreads();
        for (int s = 64; s > 0; s >>= 1) { if (o < s) sm[o] += sm[o + s]; __syncthreads(); }
        d_thpb[o] = vb - sm[0] * (1.0f / CI);
    }
}

// ---------------------------------------------------------------------------
// small fp32 chain GEMMs; chain<3> stores Whi/Wlo directly (wsplit folded).
template <int OP>
__device__ __forceinline__ float loadA(const float* __restrict__ w, int b, int m, int k) {
    if (OP == 0) return d_G[b][m][k] - d_s[b][m] * d_s[b][k] * INV_N;
    if (OP == 1) return w[m * C + k];
    if (OP == 2) return w[m * CI + k];
    return d_Q[b][m][k];
}
template <int OP>
__device__ __forceinline__ float loadB(const float* __restrict__ w, int b, int k, int n) {
    if (OP == 0) return w[n * C + k];
    if (OP == 1) return d_P[b][k][n];
    if (OP == 2) return d_M[b][n][k];
    return d_thpw[k * C + n];
}
template <int OP>
__device__ __forceinline__ void storeEl(int b, int m, int n, float v) {
    if (OP == 0) d_P[b][m][n] = v;
    if (OP == 1) d_M[b][m][n] = v;
    if (OP == 2) d_Q[b][m][n] = v;
    if (OP == 3) {
        __nv_bfloat16 h = __float2bfloat16(v);
        d_Whi[b][m][n] = h;
        d_Wlo[b][m][n] = __float2bfloat16(v - __bfloat162float(h));
    }
}
template <int OP>
__global__ void __launch_bounds__(256) k_chain(const float* __restrict__ w, int Kd) {
    constexpr bool BT = (OP == 0 || OP == 2);
    int b = blockIdx.z;
    int m0 = blockIdx.y * 32, n0 = blockIdx.x * 32;
    __shared__ float As[32][33];
    __shared__ float Bs[32][33];
    int tx = threadIdx.x & 15, ty = threadIdx.x >> 4;
    int c0 = threadIdx.x & 31, r0 = threadIdx.x >> 5;
    float a00 = 0.f, a01 = 0.f, a10 = 0.f, a11 = 0.f;
    for (int k0 = 0; k0 < Kd; k0 += 32) {
#pragma unroll
        for (int p = 0; p < 4; p++) {
            int r = r0 + p * 8;
            As[c0][r] = loadA<OP>(w, b, m0 + r, k0 + c0);
            if (BT) Bs[c0][r] = loadB<OP>(w, b, k0 + c0, n0 + r);
            else    Bs[r][c0] = loadB<OP>(w, b, k0 + r, n0 + c0);
        }
        __syncthreads();
#pragma unroll
        for (int k = 0; k < 32; k++) {
            float a0 = As[k][ty * 2], a1 = As[k][ty * 2 + 1];
            float b0 = Bs[k][tx * 2], b1 = Bs[k][tx * 2 + 1];
            a00 += a0 * b0; a01 += a0 * b1; a10 += a1 * b0; a11 += a1 * b1;
        }
        __syncthreads();
    }
    storeEl<OP>(b, m0 + ty * 2,     n0 + tx * 2,     a00);
    storeEl<OP>(b, m0 + ty * 2,     n0 + tx * 2 + 1, a01);
    storeEl<OP>(b, m0 + ty * 2 + 1, n0 + tx * 2,     a10);
    storeEl<OP>(b, m0 + ty * 2 + 1, n0 + tx * 2 + 1, a11);
}

__global__ void k_beff(const float* __restrict__ out_b) {
    int b = blockIdx.x, o = threadIdx.x;
    float acc = out_b[o];
    for (int oo = 0; oo < CI; oo++) acc += d_Q[b][o][oo] * d_thpb[oo];
    d_beff[b][o] = acc;
}

// ---------------------------------------------------------------------------
// apply: out = x + W x + beff. CTA 128(ch) x 128(sp), K=256, cp.async 2-stage.
#define APPLY_STAGE 37888u
#define APPLY_DYN   (2 * 37888)
__global__ void __launch_bounds__(256) k_apply_mma(const float* __restrict__ x,
                                                   float* __restrict__ outp) {
    extern __shared__ char smem_[];
    const int tid = threadIdx.x, wid = tid >> 5, lane = tid & 31;
    const int m0 = blockIdx.y * 128, n0 = blockIdx.x * 128, b = blockIdx.z;
    const int wm = (wid & 1) * 64, wn = (wid >> 1) * 32;
    float acc[4][4][4] = {};
    const uint32_t sb = smem_u32(smem_);

    auto issue = [&](int kc, int st) {
        const uint32_t ss = sb + (uint32_t)st * APPLY_STAGE;
        const int kb = kc * 32;
#pragma unroll
        for (int it = 0; it < 2; it++) {
            int i = tid + it * 256;
            int r = i >> 2, sg = (i & 3) * 8;             // W: 128x32
            uint32_t so = ss + (uint32_t)(r * GR_PAD + sg) * 2;
            cp16(so,          &d_Whi[b][m0 + r][kb + sg]);
            cp16(so + 10240u, &d_Wlo[b][m0 + r][kb + sg]);
            int xr = i >> 4, xs = (i & 15) * 8;           // X: 32x128
            uint32_t xo = ss + 20480u + (uint32_t)(xr * AP_BPAD + xs) * 2;
            cp16(xo,         &d_xhi[b][kb + xr][n0 + xs]);
            cp16(xo + 8704u, &d_xlo[b][kb + xr][n0 + xs]);
        }
        cp_commit();
    };

    issue(0, 0);
    for (int kc = 0; kc < 8; kc++) {
        const int st = kc & 1;
        if (kc + 1 < 8) { issue(kc + 1, st ^ 1); cp_wait<1>(); }
        else            { cp_wait<0>(); }
        __syncthreads();
        const uint32_t sWu = sb + (uint32_t)st * APPLY_STAGE;
        const uint32_t sXu = sWu + 20480u;
#pragma unroll
        for (int kk = 0; kk < 32; kk += 16) {
            uint32_t ah[4][4], al[4][4], bh[2][4], bl[2][4];
            const int arow = lane & 15, acol = kk + (lane >> 4) * 8;
#pragma unroll
            for (int i = 0; i < 4; i++) {
                uint32_t ad = sWu + (uint32_t)((wm + i * 16 + arow) * GR_PAD + acol) * 2;
                ldsm_x4(ah[i], ad);
                ldsm_x4(al[i], ad + 10240u);
            }
            const int krow = kk + (lane & 7) + ((lane >> 3) & 1) * 8;
            const int ncol = ((lane >> 4) & 1) * 8;
#pragma unroll
            for (int j = 0; j < 2; j++) {
                uint32_t bd = sXu + (uint32_t)(krow * AP_BPAD + wn + j * 16 + ncol) * 2;
                ldsm_x4_t(bh[j], bd);
                ldsm_x4_t(bl[j], bd + 8704u);
            }
#pragma unroll
            for (int i = 0; i < 4; i++)
#pragma unroll
                for (int jj = 0; jj < 4; jj++) {
                    const uint32_t* ph = &bh[jj >> 1][(jj & 1) * 2];
                    const uint32_t* pl = &bl[jj >> 1][(jj & 1) * 2];
                    mma16816(acc[i][jj], ah[i], ph);
                    mma16816(acc[i][jj], ah[i], pl);
                    mma16816(acc[i][jj], al[i], ph);
                }
        }
        __syncthreads();
    }
    // epilogue: + x + beff
#pragma unroll
    for (int i = 0; i < 4; i++) {
        int r0g = m0 + wm + i * 16 + (lane >> 2);
        float be0 = d_beff[b][r0g], be1 = d_beff[b][r0g + 8];
        const float* x0 = x + ((size_t)b * C + r0g) * NSP + n0;
        float* o0 = outp + ((size_t)b * C + r0g) * NSP + n0;
#pragma unroll
        for (int jj = 0; jj < 4; jj++) {
            int cl = wn + jj * 8 + (lane & 3) * 2;
            float2 xa = *(const float2*)(x0 + cl);
            float2 xb = *(const float2*)(x0 + 8 * NSP + cl);
            float2 oa = make_float2(acc[i][jj][0] + xa.x + be0, acc[i][jj][1] + xa.y + be0);
            float2 ob = make_float2(acc[i][jj][2] + xb.x + be1, acc[i][jj][3] + xb.y + be1);
            *(float2*)(o0 + cl) = oa;
            *(float2*)(o0 + 8 * NSP + cl) = ob;
        }
    }
}

// ---------------------------------------------------------------------------
extern "C" void kernel_launch(void* const* d_in, const int* in_sizes, int n_in,
                              void* d_out, int out_size) {
    const float* x       = (const float*)d_in[0];
    const float* g_w     = (const float*)d_in[1];
    const float* theta_w = (const float*)d_in[3];
    const float* theta_b = (const float*)d_in[4];
    const float* phi_w   = (const float*)d_in[5];
    const float* out_w   = (const float*)d_in[7];
    const float* out_b   = (const float*)d_in[8];
    float* out = (float*)d_out;

    cudaFuncSetAttribute(k_gram_mma,  cudaFuncAttributeMaxDynamicSharedMemorySize, GRAM_DYN);
    cudaFuncSetAttribute(k_apply_mma, cudaFuncAttributeMaxDynamicSharedMemorySize, APPLY_DYN);

    k_convert_rowsum<<<(BATCH * C) / 2, 256>>>(x);
    k_theta_prep<<<C, 128>>>(theta_w, theta_b);
    k_gram_mma<<<dim3(3, KS, BATCH), 256, GRAM_DYN>>>();
    k_gram_reduce<<<(BATCH * 3 * 128 * 128) / 256, 256>>>();

    k_chain<0><<<dim3(CI / 32, C  / 32, BATCH), 256>>>(g_w,   C);   // P = S g^T
    k_chain<1><<<dim3(CI / 32, CI / 32, BATCH), 256>>>(phi_w, C);   // M = phi P
    k_chain<2><<<dim3(CI / 32, C  / 32, BATCH), 256>>>(out_w, CI);  // Q = out_w M^T
    k_beff<<<BATCH, 256>>>(out_b);
    k_chain<3><<<dim3(C / 32,  C  / 32, BATCH), 256>>>(nullptr, CI); // W(hi/lo) = Q theta'

    k_apply_mma<<<dim3(NSP / 128, C / 128, BATCH), 256, APPLY_DYN>>>(x, out);
}